// round 3
// baseline (speedup 1.0000x reference)
#include <cuda_runtime.h>
#include <cuda_bf16.h>
#include <mma.h>
#include <math.h>

using namespace nvcuda;

// ---------------------------------------------------------------------------
// DGCNN forward.  B=8, N=1024, KNN=20.
// Features stored n-major. Stage outputs written directly into concat buffer
// Xc[b][n][512] at column offsets {0,64,128,256}.
// edge_conv factorization:  y[o,n,k] = (wd@x)[o,idx[n,k]] + ((wc-wd)@x)[o,n]
// All GEMMs: wmma tf32x3 (split fp32 -> hi+lo, 3 MMA terms) == fp32 accuracy
// on the tensor pipe.
// ---------------------------------------------------------------------------

#define BB   8
#define NN   1024
#define KNN  20

// ------------------------- scratch (device globals) ------------------------
__device__ float g_inner[BB * NN * NN];     // 32MB: Gram matrices / conv5 out
__device__ float g_xx[BB * NN];
__device__ int   g_idx[BB * NN * KNN];
__device__ float g_AB[BB * NN * 512];       // [wd;wcd] @ x  (n-major, 2*O cols)
__device__ float g_Xc[BB * NN * 512];       // concat buffer (stage outputs)
__device__ float g_wbuf[96000];             // stacked [wd;wcd] for all stages
__device__ float g_gpool[BB * NN];

// stacked-weight offsets (floats)
#define W1_OFF 0        // 128*3   = 384
#define W2_OFF 384      // 128*64  = 8192
#define W3_OFF 8576     // 256*64  = 16384
#define W4_OFF 24960    // 512*128 = 65536
#define W_TOTAL 90496

// --------------------------- weight split (all stages) -----------------------
__device__ __forceinline__ void wsplit_one(const float* w, float* out,
                                           int O, int C, int i)
{
    int r = i / C, c = i % C;
    if (r < O) out[i] = w[(long)r * 2 * C + c];
    else {
        int o = r - O;
        out[i] = w[(long)o * 2 * C + C + c] - w[(long)o * 2 * C + c];
    }
}

__global__ void wsplit_all_kernel(const float* __restrict__ w1, const float* __restrict__ w2,
                                  const float* __restrict__ w3, const float* __restrict__ w4,
                                  float* __restrict__ out)
{
    int i = blockIdx.x * 256 + threadIdx.x;
    if (i >= W_TOTAL) return;
    if (i < W2_OFF)      wsplit_one(w1, out + W1_OFF, 64,  3,   i - W1_OFF);
    else if (i < W3_OFF) wsplit_one(w2, out + W2_OFF, 64,  64,  i - W2_OFF);
    else if (i < W4_OFF) wsplit_one(w3, out + W3_OFF, 128, 64,  i - W3_OFF);
    else                 wsplit_one(w4, out + W4_OFF, 256, 128, i - W4_OFF);
}

// --------------------------- row squared norms ------------------------------
__global__ void rownorm_kernel(const float* __restrict__ X, float* __restrict__ xx,
                               int C, int ldx)
{
    int i = blockIdx.x * blockDim.x + threadIdx.x;   // over B*N
    if (i < BB * NN) {
        const float* r = X + (long)i * ldx;
        float s = 0.f;
        for (int c = 0; c < C; c++) s += r[c] * r[c];
        xx[i] = s;
    }
}

// --------------------------- tf32x3 wmma GEMM (NT) ---------------------------
// C[m][n] = sum_k A[m][k] * B[n][k]
// CTA tile 128x64, 8 warps (4x2), warp tile 32x32 = 2x2 m16n16k8 fragments.
// fp32 operands split hi/lo (tf32) -> 3 MMA terms -> fp32-level accuracy.
#define GBM 128
#define GBN 64
#define GKC 16
#define GLD (GKC + 4)

__global__ __launch_bounds__(256) void gemm_tf32x3(
        const float* __restrict__ A, const float* __restrict__ B,
        float* __restrict__ C, int K,
        int lda, int ldb, int ldc,
        long sA, long sB, long sC)
{
    int bz = blockIdx.z;
    A += (long)bz * sA;
    B += (long)bz * sB;
    C += (long)bz * sC;

    int m0 = blockIdx.x * GBM;
    int n0 = blockIdx.y * GBN;

    __shared__ __align__(16) float As[GBM][GLD];
    __shared__ __align__(16) float Bs[GBN][GLD];

    int tid  = threadIdx.x;
    int wid  = tid >> 5;
    int wm   = (wid >> 1) * 32;     // warp row offset in tile (0,32,64,96)
    int wn   = (wid & 1)  * 32;     // warp col offset (0,32)

    typedef wmma::fragment<wmma::matrix_a, 16, 16, 8, wmma::precision::tf32, wmma::row_major> FragA;
    typedef wmma::fragment<wmma::matrix_b, 16, 16, 8, wmma::precision::tf32, wmma::col_major> FragB;
    typedef wmma::fragment<wmma::accumulator, 16, 16, 8, float> FragC;

    FragC c[2][2];
#pragma unroll
    for (int i = 0; i < 2; i++)
#pragma unroll
        for (int j = 0; j < 2; j++) wmma::fill_fragment(c[i][j], 0.f);

    for (int k0 = 0; k0 < K; k0 += GKC) {
        // fill A tile: 128x16, scalar guarded loads (8 per thread)
#pragma unroll
        for (int l0 = 0; l0 < (GBM * GKC) / 256; l0++) {
            int e = tid + l0 * 256;
            int r = e >> 4, cc = e & 15;
            int k = k0 + cc;
            As[r][cc] = (k < K) ? A[(long)(m0 + r) * lda + k] : 0.f;
        }
        // fill B tile: 64x16 (4 per thread)
#pragma unroll
        for (int l0 = 0; l0 < (GBN * GKC) / 256; l0++) {
            int e = tid + l0 * 256;
            int r = e >> 4, cc = e & 15;
            int k = k0 + cc;
            Bs[r][cc] = (k < K) ? B[(long)(n0 + r) * ldb + k] : 0.f;
        }
        __syncthreads();

#pragma unroll
        for (int ks = 0; ks < GKC; ks += 8) {
            FragA a_hi[2], a_lo[2];
            FragB b_hi[2], b_lo[2];
#pragma unroll
            for (int i = 0; i < 2; i++) {
                wmma::load_matrix_sync(a_hi[i], &As[wm + i * 16][ks], GLD);
#pragma unroll
                for (int e = 0; e < a_hi[i].num_elements; e++) {
                    float v = a_hi[i].x[e];
                    float h = wmma::__float_to_tf32(v);
                    a_hi[i].x[e] = h;
                    a_lo[i].x[e] = wmma::__float_to_tf32(v - h);
                }
            }
#pragma unroll
            for (int j = 0; j < 2; j++) {
                wmma::load_matrix_sync(b_hi[j], &Bs[wn + j * 16][ks], GLD);
#pragma unroll
                for (int e = 0; e < b_hi[j].num_elements; e++) {
                    float v = b_hi[j].x[e];
                    float h = wmma::__float_to_tf32(v);
                    b_hi[j].x[e] = h;
                    b_lo[j].x[e] = wmma::__float_to_tf32(v - h);
                }
            }
#pragma unroll
            for (int i = 0; i < 2; i++)
#pragma unroll
                for (int j = 0; j < 2; j++) {
                    wmma::mma_sync(c[i][j], a_hi[i], b_lo[j], c[i][j]);
                    wmma::mma_sync(c[i][j], a_lo[i], b_hi[j], c[i][j]);
                    wmma::mma_sync(c[i][j], a_hi[i], b_hi[j], c[i][j]);
                }
        }
        __syncthreads();
    }

#pragma unroll
    for (int i = 0; i < 2; i++)
#pragma unroll
        for (int j = 0; j < 2; j++)
            wmma::store_matrix_sync(&C[(long)(m0 + wm + i * 16) * ldc + n0 + wn + j * 16],
                                    c[i][j], ldc, wmma::mem_row_major);
}

// --------------------------- top-k (k=20), warp per row ----------------------
// dist[m] = 2*inner[n][m] - xx[n] - xx[m]; iterative argmax, tie -> lower idx
__global__ void topk_kernel(const float* __restrict__ inner,
                            const float* __restrict__ xx,
                            int* __restrict__ idx)
{
    int warp = threadIdx.x >> 5, lane = threadIdx.x & 31;
    int n = blockIdx.x * 8 + warp;
    int b = blockIdx.y;

    const float* row = inner + ((long)b * NN + n) * NN;
    float xn = xx[b * NN + n];

    float d[32];
#pragma unroll
    for (int j = 0; j < 32; j++) {
        int m = j * 32 + lane;
        d[j] = 2.f * row[m] - xn - xx[b * NN + m];
    }

    int* orow = idx + ((long)b * NN + n) * KNN;
    for (int it = 0; it < KNN; it++) {
        float bv = d[0]; int bj = 0;
#pragma unroll
        for (int j = 1; j < 32; j++)
            if (d[j] > bv) { bv = d[j]; bj = j; }
        int bm = bj * 32 + lane;
#pragma unroll
        for (int off = 16; off; off >>= 1) {
            float ov = __shfl_xor_sync(0xffffffffu, bv, off);
            int   om = __shfl_xor_sync(0xffffffffu, bm, off);
            if (ov > bv || (ov == bv && om < bm)) { bv = ov; bm = om; }
        }
        if (lane == 0) orow[it] = bm;
        if ((bm & 31) == lane) {
            int wj = bm >> 5;
#pragma unroll
            for (int j = 0; j < 32; j++)
                if (j == wj) d[j] = -INFINITY;
        }
    }
}

// --------------------------- gather + bn + lrelu + max ------------------------
__global__ void gathermax_kernel(const float* __restrict__ AB,
                                 const int* __restrict__ idx,
                                 const float* __restrict__ bias,
                                 const float* __restrict__ gg,
                                 const float* __restrict__ bb,
                                 float* __restrict__ Xout, int O)
{
    int n = blockIdx.x, b = blockIdx.y;
    __shared__ int nb[KNN];
    if (threadIdx.x < KNN)
        nb[threadIdx.x] = idx[((long)b * NN + n) * KNN + threadIdx.x];
    __syncthreads();

    const float rs = rsqrtf(1.f + 1e-5f);
    int twoO = 2 * O;
    long rowbase = ((long)b * NN + n) * twoO;
    for (int o = threadIdx.x; o < O; o += blockDim.x) {
        float base = AB[rowbase + O + o] + (bias ? bias[o] : 0.f);
        float gs = gg[o] * rs;
        float bo = bb[o];
        float acc = -INFINITY;
#pragma unroll
        for (int k = 0; k < KNN; k++) {
            float a = AB[((long)b * NN + nb[k]) * twoO + o];
            float v = (a + base) * gs + bo;
            v = (v >= 0.f) ? v : 0.01f * v;
            acc = fmaxf(acc, v);
        }
        Xout[((long)b * NN + n) * 512 + o] = acc;
    }
}

// --------------------------- column max over n --------------------------------
__global__ void maxcol_kernel(const float* __restrict__ e, float* __restrict__ gpool)
{
    int b = blockIdx.y;
    int o = blockIdx.x * 256 + threadIdx.x;
    float m = -INFINITY;
    const float* eb = e + (long)b * NN * NN;
    for (int n = 0; n < NN; n++)
        m = fmaxf(m, eb[(long)n * NN + o]);
    gpool[b * NN + o] = m;
}

// --------------------------- MLP head -----------------------------------------
__global__ void mlp_head_kernel(const float* __restrict__ gpool,
                                const float* __restrict__ w1,
                                const float* __restrict__ g6, const float* __restrict__ b6,
                                const float* __restrict__ w2, const float* __restrict__ b2v,
                                const float* __restrict__ g7, const float* __restrict__ b7,
                                const float* __restrict__ w3, const float* __restrict__ b3v,
                                float* __restrict__ out)
{
    int b = blockIdx.x;
    int t = threadIdx.x;    // 512 threads
    __shared__ float s0[1024];
    __shared__ float s1[512];
    __shared__ float s2[256];

    for (int i = t; i < 1024; i += 512) s0[i] = gpool[b * 1024 + i];
    __syncthreads();

    const float rs = rsqrtf(1.f + 1e-5f);
    {
        const float* wr = w1 + (long)t * 1024;
        float acc = 0.f;
        for (int k = 0; k < 1024; k++) acc += s0[k] * wr[k];
        acc = acc * (g6[t] * rs) + b6[t];
        s1[t] = (acc >= 0.f) ? acc : 0.01f * acc;
    }
    __syncthreads();

    if (t < 256) {
        const float* wr = w2 + (long)t * 512;
        float acc = 0.f;
        for (int k = 0; k < 512; k++) acc += s1[k] * wr[k];
        acc += b2v[t];
        acc = acc * (g7[t] * rs) + b7[t];
        s2[t] = (acc >= 0.f) ? acc : 0.01f * acc;
    }
    __syncthreads();

    if (t < 40) {
        const float* wr = w3 + (long)t * 256;
        float acc = 0.f;
        for (int k = 0; k < 256; k++) acc += s2[k] * wr[k];
        out[b * 40 + t] = acc + b3v[t];
    }
}

// ---------------------------------------------------------------------------
// host side
// ---------------------------------------------------------------------------
static void run_edge_stage(const float* X, int ldx, long strideX, int C, int O,
                           const float* wcomb,      // stacked [wd;wcd], 2O x C
                           const float* bias,
                           const float* gg, const float* bbv,
                           float* Xout,             // Xc slice base (ld 512)
                           float* inner, float* xxp, int* idxp, float* ABp)
{
    rownorm_kernel<<<(BB * NN + 255) / 256, 256>>>(X, xxp, C, ldx);

    // Gram: inner[b] = X X^T  (1024x1024, K=C)
    dim3 gi(NN / GBM, NN / GBN, BB);
    gemm_tf32x3<<<gi, 256>>>(X, X, inner, C, ldx, ldx, NN,
                             strideX, strideX, (long)NN * NN);

    topk_kernel<<<dim3(NN / 8, BB), 256>>>(inner, xxp, idxp);

    // features: AB[b] = X @ [wd;wcd]^T   (1024 x 2O)
    int twoO = 2 * O;
    dim3 ga(NN / GBM, twoO / GBN, BB);
    gemm_tf32x3<<<ga, 256>>>(X, wcomb, ABp, C, ldx, C, twoO,
                             strideX, 0, (long)NN * twoO);

    gathermax_kernel<<<dim3(NN, BB), 256>>>(ABp, idxp, bias, gg, bbv, Xout, O);
}

extern "C" void kernel_launch(void* const* d_in, const int* in_sizes, int n_in,
                              void* d_out, int out_size)
{
    const float* x       = (const float*)d_in[0];    // (8,1024,3)
    const float* conv1_w = (const float*)d_in[1];
    const float* conv1_b = (const float*)d_in[2];
    const float* bn1_g   = (const float*)d_in[3];
    const float* bn1_b   = (const float*)d_in[4];
    const float* conv2_w = (const float*)d_in[5];
    const float* bn2_g   = (const float*)d_in[6];
    const float* bn2_b   = (const float*)d_in[7];
    const float* conv3_w = (const float*)d_in[8];
    const float* bn3_g   = (const float*)d_in[9];
    const float* bn3_b   = (const float*)d_in[10];
    const float* conv4_w = (const float*)d_in[11];
    const float* bn4_g   = (const float*)d_in[12];
    const float* bn4_b   = (const float*)d_in[13];
    const float* conv5_w = (const float*)d_in[14];
    const float* lin1_w  = (const float*)d_in[15];
    const float* bn6_g   = (const float*)d_in[16];
    const float* bn6_b   = (const float*)d_in[17];
    const float* lin2_w  = (const float*)d_in[18];
    const float* lin2_b  = (const float*)d_in[19];
    const float* bn7_g   = (const float*)d_in[20];
    const float* bn7_b   = (const float*)d_in[21];
    const float* lin3_w  = (const float*)d_in[22];
    const float* lin3_b  = (const float*)d_in[23];
    float* out = (float*)d_out;

    float *inner, *xxp, *ABp, *Xc, *wbuf, *gp;
    int* idxp;
    cudaGetSymbolAddress((void**)&inner, g_inner);
    cudaGetSymbolAddress((void**)&xxp,   g_xx);
    cudaGetSymbolAddress((void**)&idxp,  g_idx);
    cudaGetSymbolAddress((void**)&ABp,   g_AB);
    cudaGetSymbolAddress((void**)&Xc,    g_Xc);
    cudaGetSymbolAddress((void**)&wbuf,  g_wbuf);
    cudaGetSymbolAddress((void**)&gp,    g_gpool);

    wsplit_all_kernel<<<(W_TOTAL + 255) / 256, 256>>>(conv1_w, conv2_w, conv3_w, conv4_w, wbuf);

    // edge conv stages (outputs go straight into concat slices of Xc)
    run_edge_stage(x,        3,   (long)NN * 3,   3,   64,  wbuf + W1_OFF, conv1_b,
                   bn1_g, bn1_b, Xc + 0,   inner, xxp, idxp, ABp);
    run_edge_stage(Xc + 0,   512, (long)NN * 512, 64,  64,  wbuf + W2_OFF, nullptr,
                   bn2_g, bn2_b, Xc + 64,  inner, xxp, idxp, ABp);
    run_edge_stage(Xc + 64,  512, (long)NN * 512, 64,  128, wbuf + W3_OFF, nullptr,
                   bn3_g, bn3_b, Xc + 128, inner, xxp, idxp, ABp);
    run_edge_stage(Xc + 128, 512, (long)NN * 512, 128, 256, wbuf + W4_OFF, nullptr,
                   bn4_g, bn4_b, Xc + 256, inner, xxp, idxp, ABp);

    // conv5:  e[b] = Xc @ conv5_w^T  (1024 x 1024, K=512), then max over n
    dim3 g5(NN / GBM, NN / GBN, BB);
    gemm_tf32x3<<<g5, 256>>>(Xc, conv5_w, inner, 512, 512, 512, NN,
                             (long)NN * 512, 0, (long)NN * NN);
    maxcol_kernel<<<dim3(NN / 256, BB), 256>>>(inner, gp);

    // MLP head
    mlp_head_kernel<<<BB, 512>>>(gp, lin1_w, bn6_g, bn6_b,
                                 lin2_w, lin2_b, bn7_g, bn7_b,
                                 lin3_w, lin3_b, out);
}

// round 10
// speedup vs baseline: 1.0900x; 1.0900x over previous
#include <cuda_runtime.h>
#include <cuda_bf16.h>
#include <mma.h>
#include <math.h>
#include <stdint.h>

using namespace nvcuda;

// ---------------------------------------------------------------------------
// DGCNN forward.  B=8, N=1024, KNN=20.
// edge_conv factorization:  y[o,n,k] = (wd@x)[o,idx[n,k]] + ((wc-wd)@x)[o,n]
// HYBRID precision:
//   - Gram / KNN distances: fp32 FFMA GEMM (tie-flip-sensitive -> exact path)
//   - feature GEMMs + conv5: wmma bf16 m16n16k16 with 3-segment split (K'=3K):
//       A' = [hi|lo|hi],  B' = [hi|hi|lo]  ->  hihi + lohi + hilo
// ---------------------------------------------------------------------------

#define BB   8
#define NN   1024
#define KNN  20

// ------------------------- scratch (device globals) ------------------------
__device__ float g_inner[BB * NN * NN];     // 32MB: Gram matrices / conv5 out
__device__ float g_xx[BB * NN];
__device__ int   g_idx[BB * NN * KNN];
__device__ float g_AB[BB * NN * 512];       // [wd;wcd] @ x  (n-major, 2*O cols)
__device__ float g_Xc[BB * NN * 512];       // concat buffer (stage outputs)
__device__ float g_wbuf[96000];             // stacked [wd;wcd] fp32
__device__ float g_gpool[BB * NN];

// bf16 3-segment buffers (16-byte aligned for uint4 loads)
__device__ __align__(16) __nv_bfloat16 g_XA[BB * NN * 1536];   // layout A
__device__ __align__(16) __nv_bfloat16 g_Wb[282624];           // stage weights, layout B
__device__ __align__(16) __nv_bfloat16 g_W5b[1024 * 1536];     // conv5 weights, layout B

// stacked fp32 weight offsets
#define W1_OFF 0
#define W2_OFF 384
#define W3_OFF 8576
#define W4_OFF 24960
#define W_TOTAL 90496
// bf16 stage-weight offsets (rows x 3*Kp)
#define WB1_OFF 0        // 128 x 96
#define WB2_OFF 12288    // 128 x 192
#define WB3_OFF 36864    // 256 x 192
#define WB4_OFF 86016    // 512 x 384  -> end 282624

// --------------------------- weight split (fp32) ----------------------------
__device__ __forceinline__ void wsplit_one(const float* w, float* out,
                                           int O, int C, int i)
{
    int r = i / C, c = i % C;
    if (r < O) out[i] = w[(long)r * 2 * C + c];
    else {
        int o = r - O;
        out[i] = w[(long)o * 2 * C + C + c] - w[(long)o * 2 * C + c];
    }
}

__global__ void wsplit_all_kernel(const float* __restrict__ w1, const float* __restrict__ w2,
                                  const float* __restrict__ w3, const float* __restrict__ w4,
                                  float* __restrict__ out)
{
    int i = blockIdx.x * 256 + threadIdx.x;
    if (i >= W_TOTAL) return;
    if (i < W2_OFF)      wsplit_one(w1, out + W1_OFF, 64,  3,   i - W1_OFF);
    else if (i < W3_OFF) wsplit_one(w2, out + W2_OFF, 64,  64,  i - W2_OFF);
    else if (i < W4_OFF) wsplit_one(w3, out + W3_OFF, 128, 64,  i - W3_OFF);
    else                 wsplit_one(w4, out + W4_OFF, 256, 128, i - W4_OFF);
}

// --------------------------- fp32 -> bf16 3-segment --------------------------
// src [R][K] (row stride ldsrc) -> dst [R][3*Kp]; segment s = c / Kp.
// Segment 'loseg' holds lo = bf16(v - bf16(v)); other segments hold hi.
// layout A: loseg=1  ([hi|lo|hi]);  layout B: loseg=2  ([hi|hi|lo]).
__global__ void tobf16_kernel(const float* __restrict__ src, int ldsrc, int K, int Kp,
                              int loseg, __nv_bfloat16* __restrict__ dst, int total)
{
    int W = 3 * Kp;
    for (int i = blockIdx.x * 256 + threadIdx.x; i < total; i += gridDim.x * 256) {
        int r = i / W, c = i % W;
        int seg = c / Kp;
        int k = c - seg * Kp;
        __nv_bfloat16 outv = __float2bfloat16(0.f);
        if (k < K) {
            float v = src[(long)r * ldsrc + k];
            __nv_bfloat16 h = __float2bfloat16(v);
            if (seg == loseg) outv = __float2bfloat16(v - __bfloat162float(h));
            else              outv = h;
        }
        dst[(long)r * W + c] = outv;
    }
}

// --------------------------- row squared norms ------------------------------
__global__ void rownorm_kernel(const float* __restrict__ X, float* __restrict__ xx,
                               int C, int ldx)
{
    int i = blockIdx.x * blockDim.x + threadIdx.x;
    if (i < BB * NN) {
        const float* r = X + (long)i * ldx;
        float s = 0.f;
        for (int c = 0; c < C; c++) s += r[c] * r[c];
        xx[i] = s;
    }
}

// --------------------------- fp32 tiled GEMM (NT) ----------------------------
// C[m][n] = sum_k A[m][k] * B[n][k]   (used ONLY for the Gram matrices)
// BM=128, BN=64, BK=16, 256 threads, 8x4 register tile.
#define FBM 128
#define FBN 64
#define FBK 16
#define FPAD 4

__global__ __launch_bounds__(256) void gemm_nt(
        const float* __restrict__ A, const float* __restrict__ B,
        float* __restrict__ C, int M, int N, int K,
        int lda, int ldb, int ldc,
        long sA, long sB, long sC)
{
    int bz = blockIdx.z;
    A += (long)bz * sA;
    B += (long)bz * sB;
    C += (long)bz * sC;

    int m0 = blockIdx.x * FBM;
    int n0 = blockIdx.y * FBN;

    __shared__ float As[FBK][FBM + FPAD];
    __shared__ float Bs[FBK][FBN + FPAD];

    int tid = threadIdx.x;
    int ty = tid >> 4;          // 0..15 -> 8 rows each
    int tx = tid & 15;          // 0..15 -> 4 cols each

    float acc[8][4];
#pragma unroll
    for (int i = 0; i < 8; i++)
#pragma unroll
        for (int j = 0; j < 4; j++) acc[i][j] = 0.f;

    for (int k0 = 0; k0 < K; k0 += FBK) {
#pragma unroll
        for (int l0 = 0; l0 < (FBM * FBK) / 256; l0++) {
            int l = tid + l0 * 256;
            int r = l >> 4, c = l & 15;
            int ki = k0 + c;
            As[c][r] = (ki < K) ? A[(long)(m0 + r) * lda + ki] : 0.f;
        }
#pragma unroll
        for (int l0 = 0; l0 < (FBN * FBK) / 256; l0++) {
            int l = tid + l0 * 256;
            int r = l >> 4, c = l & 15;
            int ki = k0 + c;
            Bs[c][r] = (ki < K) ? B[(long)(n0 + r) * ldb + ki] : 0.f;
        }
        __syncthreads();

#pragma unroll
        for (int kk = 0; kk < FBK; kk++) {
            float4 a0 = *(const float4*)&As[kk][ty * 8];
            float4 a1 = *(const float4*)&As[kk][ty * 8 + 4];
            float4 bv = *(const float4*)&Bs[kk][tx * 4];
            float av[8] = {a0.x, a0.y, a0.z, a0.w, a1.x, a1.y, a1.z, a1.w};
            float bw[4] = {bv.x, bv.y, bv.z, bv.w};
#pragma unroll
            for (int i = 0; i < 8; i++)
#pragma unroll
                for (int j = 0; j < 4; j++) acc[i][j] += av[i] * bw[j];
        }
        __syncthreads();
    }

#pragma unroll
    for (int i = 0; i < 8; i++) {
        long mi = m0 + ty * 8 + i;
        float4 v = make_float4(acc[i][0], acc[i][1], acc[i][2], acc[i][3]);
        *(float4*)&C[mi * ldc + n0 + tx * 4] = v;
    }
}

// --------------------------- wmma bf16 GEMM (NT) -----------------------------
// C[m][n] = sum_k A[m][k]*B[n][k], A/B bf16 (3-seg layout, n-major rows), C fp32.
// CTA tile 128x128, 8 warps: warp tile 64x32 (4x2 m16n16k16 frags). BK=32.
#define TBM 128
#define TBN 128
#define TKB 32
#define SLD 40          // smem row stride in bf16 (32 + 8 pad, 16B aligned)

__global__ __launch_bounds__(256) void gemm_bf16(
        const __nv_bfloat16* __restrict__ A, const __nv_bfloat16* __restrict__ B,
        float* __restrict__ C, int lda, int ldb, int ldc, int K,
        long sA, long sB, long sC)
{
    int bz = blockIdx.z;
    A += (long)bz * sA;
    B += (long)bz * sB;
    C += (long)bz * sC;

    int m0 = blockIdx.x * TBM;
    int n0 = blockIdx.y * TBN;

    __shared__ __align__(16) __nv_bfloat16 As[TBM * SLD];
    __shared__ __align__(16) __nv_bfloat16 Bs[TBN * SLD];

    int tid = threadIdx.x;
    int wid = tid >> 5;
    int wr  = (wid & 1) * 64;       // warp row offset
    int wc  = (wid >> 1) * 32;      // warp col offset

    typedef wmma::fragment<wmma::matrix_a, 16, 16, 16, __nv_bfloat16, wmma::row_major> FragA;
    typedef wmma::fragment<wmma::matrix_b, 16, 16, 16, __nv_bfloat16, wmma::col_major> FragB;
    typedef wmma::fragment<wmma::accumulator, 16, 16, 16, float> FragC;

    FragC acc[4][2];
#pragma unroll
    for (int i = 0; i < 4; i++)
#pragma unroll
        for (int j = 0; j < 2; j++) wmma::fill_fragment(acc[i][j], 0.f);

    for (int k0 = 0; k0 < K; k0 += TKB) {
        // A tile: 128x32 bf16 = 512 uint4; 2 per thread
#pragma unroll
        for (int it = 0; it < 2; it++) {
            int e = tid + it * 256;
            int r = e >> 2, c = (e & 3) * 8;
            *(uint4*)&As[r * SLD + c] =
                *(const uint4*)(A + (long)(m0 + r) * lda + k0 + c);
        }
#pragma unroll
        for (int it = 0; it < 2; it++) {
            int e = tid + it * 256;
            int r = e >> 2, c = (e & 3) * 8;
            *(uint4*)&Bs[r * SLD + c] =
                *(const uint4*)(B + (long)(n0 + r) * ldb + k0 + c);
        }
        __syncthreads();

#pragma unroll
        for (int ks = 0; ks < TKB; ks += 16) {
            FragA a[4];
            FragB b[2];
#pragma unroll
            for (int i = 0; i < 4; i++)
                wmma::load_matrix_sync(a[i], &As[(wr + i * 16) * SLD + ks], SLD);
#pragma unroll
            for (int j = 0; j < 2; j++)
                wmma::load_matrix_sync(b[j], &Bs[(wc + j * 16) * SLD + ks], SLD);
#pragma unroll
            for (int i = 0; i < 4; i++)
#pragma unroll
                for (int j = 0; j < 2; j++)
                    wmma::mma_sync(acc[i][j], a[i], b[j], acc[i][j]);
        }
        __syncthreads();
    }

#pragma unroll
    for (int i = 0; i < 4; i++)
#pragma unroll
        for (int j = 0; j < 2; j++)
            wmma::store_matrix_sync(&C[(long)(m0 + wr + i * 16) * ldc + n0 + wc + j * 16],
                                    acc[i][j], ldc, wmma::mem_row_major);
}

// --------------------------- top-k (k=20), warp per row ----------------------
// sortable-u32 distances, cached per-lane local max, REDUX per iteration.
__global__ void topk_kernel(const float* __restrict__ inner,
                            const float* __restrict__ xx,
                            int* __restrict__ idx)
{
    int warp = threadIdx.x >> 5, lane = threadIdx.x & 31;
    int n = blockIdx.x * 8 + warp;
    int b = blockIdx.y;

    const float* row = inner + ((long)b * NN + n) * NN;
    float xn = xx[b * NN + n];

    unsigned u[32];
#pragma unroll
    for (int j = 0; j < 32; j++) {
        int m = j * 32 + lane;
        float dv = 2.f * row[m] - xn - xx[b * NN + m];
        unsigned s = __float_as_uint(dv);
        u[j] = (s & 0x80000000u) ? ~s : (s | 0x80000000u);
    }
    unsigned um = u[0]; int jm = 0;
#pragma unroll
    for (int j = 1; j < 32; j++)
        if (u[j] > um) { um = u[j]; jm = j; }

    int* orow = idx + ((long)b * NN + n) * KNN;
    for (int it = 0; it < KNN; it++) {
        unsigned w = __reduce_max_sync(0xffffffffu, um);
        unsigned cand = (um == w) ? (unsigned)(jm * 32 + lane) : 0x7fffffffu;
        unsigned mwin = __reduce_min_sync(0xffffffffu, cand);
        if (lane == 0) orow[it] = (int)mwin;
        if ((mwin & 31) == lane) {
            int wj = (int)(mwin >> 5);
#pragma unroll
            for (int j = 0; j < 32; j++)
                if (j == wj) u[j] = 0;
            um = u[0]; jm = 0;
#pragma unroll
            for (int j = 1; j < 32; j++)
                if (u[j] > um) { um = u[j]; jm = j; }
        }
    }
}

// --------------------------- gather + bn + lrelu + max ------------------------
__global__ void gathermax_kernel(const float* __restrict__ AB,
                                 const int* __restrict__ idx,
                                 const float* __restrict__ bias,
                                 const float* __restrict__ gg,
                                 const float* __restrict__ bb,
                                 float* __restrict__ Xout, int O)
{
    int n = blockIdx.x, b = blockIdx.y;
    __shared__ int nb[KNN];
    if (threadIdx.x < KNN)
        nb[threadIdx.x] = idx[((long)b * NN + n) * KNN + threadIdx.x];
    __syncthreads();

    const float rs = rsqrtf(1.f + 1e-5f);
    int twoO = 2 * O;
    long rowbase = ((long)b * NN + n) * twoO;
    for (int o = threadIdx.x; o < O; o += blockDim.x) {
        float base = AB[rowbase + O + o] + (bias ? bias[o] : 0.f);
        float gs = gg[o] * rs;
        float bo = bb[o];
        float acc = -INFINITY;
#pragma unroll
        for (int k = 0; k < KNN; k++) {
            float a = AB[((long)b * NN + nb[k]) * twoO + o];
            float v = (a + base) * gs + bo;
            v = (v >= 0.f) ? v : 0.01f * v;
            acc = fmaxf(acc, v);
        }
        Xout[((long)b * NN + n) * 512 + o] = acc;
    }
}

// --------------------------- column max over n --------------------------------
__global__ void maxcol_kernel(const float* __restrict__ e, float* __restrict__ gpool)
{
    int b = blockIdx.y;
    int o = blockIdx.x * 256 + threadIdx.x;
    float m = -INFINITY;
    const float* eb = e + (long)b * NN * NN;
    for (int n = 0; n < NN; n++)
        m = fmaxf(m, eb[(long)n * NN + o]);
    gpool[b * NN + o] = m;
}

// --------------------------- MLP head -----------------------------------------
__global__ void mlp_head_kernel(const float* __restrict__ gpool,
                                const float* __restrict__ w1,
                                const float* __restrict__ g6, const float* __restrict__ b6,
                                const float* __restrict__ w2, const float* __restrict__ b2v,
                                const float* __restrict__ g7, const float* __restrict__ b7,
                                const float* __restrict__ w3, const float* __restrict__ b3v,
                                float* __restrict__ out)
{
    int b = blockIdx.x;
    int t = threadIdx.x;    // 512 threads
    __shared__ float s0[1024];
    __shared__ float s1[512];
    __shared__ float s2[256];

    for (int i = t; i < 1024; i += 512) s0[i] = gpool[b * 1024 + i];
    __syncthreads();

    const float rs = rsqrtf(1.f + 1e-5f);
    {
        const float* wr = w1 + (long)t * 1024;
        float acc = 0.f;
        for (int k = 0; k < 1024; k++) acc += s0[k] * wr[k];
        acc = acc * (g6[t] * rs) + b6[t];
        s1[t] = (acc >= 0.f) ? acc : 0.01f * acc;
    }
    __syncthreads();

    if (t < 256) {
        const float* wr = w2 + (long)t * 512;
        float acc = 0.f;
        for (int k = 0; k < 512; k++) acc += s1[k] * wr[k];
        acc += b2v[t];
        acc = acc * (g7[t] * rs) + b7[t];
        s2[t] = (acc >= 0.f) ? acc : 0.01f * acc;
    }
    __syncthreads();

    if (t < 40) {
        const float* wr = w3 + (long)t * 256;
        float acc = 0.f;
        for (int k = 0; k < 256; k++) acc += s2[k] * wr[k];
        out[b * 40 + t] = acc + b3v[t];
    }
}

// ---------------------------------------------------------------------------
// host side
// ---------------------------------------------------------------------------
static void launch_tobf16(const float* src, int ldsrc, int K, int Kp, int loseg,
                          __nv_bfloat16* dst, int total)
{
    int nblk = (total + 255) / 256; if (nblk > 4096) nblk = 4096;
    tobf16_kernel<<<nblk, 256>>>(src, ldsrc, K, Kp, loseg, dst, total);
}

static void run_edge_stage(const float* X, int ldx, int C, int O,
                           const __nv_bfloat16* Wbst,   // [2O][3*Kp] layout B
                           const float* bias,
                           const float* gg, const float* bbv,
                           float* Xout,                 // Xc slice base (ld 512)
                           float* inner, float* xxp, int* idxp, float* ABp,
                           __nv_bfloat16* XA)
{
    rownorm_kernel<<<(BB * NN + 255) / 256, 256>>>(X, xxp, C, ldx);

    // Gram in fp32: inner[b] = X X^T  (exact KNN path)
    dim3 gi(NN / FBM, NN / FBN, BB);
    gemm_nt<<<gi, 256>>>(X, X, inner, NN, NN, C, ldx, ldx, NN,
                         (long)NN * ldx, (long)NN * ldx, (long)NN * NN);

    topk_kernel<<<dim3(NN / 8, BB), 256>>>(inner, xxp, idxp);

    // features in bf16 split: AB[b] = XA @ Wbst^T  (1024 x 2O)
    int Kp = ((C + 31) / 32) * 32;
    int W  = 3 * Kp;
    launch_tobf16(X, ldx, C, Kp, 1, XA, BB * NN * W);   // layout A: [hi|lo|hi]

    int twoO = 2 * O;
    dim3 ga(NN / TBM, (twoO + TBN - 1) / TBN, BB);
    gemm_bf16<<<ga, 256>>>(XA, Wbst, ABp, W, W, twoO, W,
                           (long)NN * W, 0, (long)NN * twoO);

    gathermax_kernel<<<dim3(NN, BB), 256>>>(ABp, idxp, bias, gg, bbv, Xout, O);
}

extern "C" void kernel_launch(void* const* d_in, const int* in_sizes, int n_in,
                              void* d_out, int out_size)
{
    const float* x       = (const float*)d_in[0];    // (8,1024,3)
    const float* conv1_w = (const float*)d_in[1];
    const float* conv1_b = (const float*)d_in[2];
    const float* bn1_g   = (const float*)d_in[3];
    const float* bn1_b   = (const float*)d_in[4];
    const float* conv2_w = (const float*)d_in[5];
    const float* bn2_g   = (const float*)d_in[6];
    const float* bn2_b   = (const float*)d_in[7];
    const float* conv3_w = (const float*)d_in[8];
    const float* bn3_g   = (const float*)d_in[9];
    const float* bn3_b   = (const float*)d_in[10];
    const float* conv4_w = (const float*)d_in[11];
    const float* bn4_g   = (const float*)d_in[12];
    const float* bn4_b   = (const float*)d_in[13];
    const float* conv5_w = (const float*)d_in[14];
    const float* lin1_w  = (const float*)d_in[15];
    const float* bn6_g   = (const float*)d_in[16];
    const float* bn6_b   = (const float*)d_in[17];
    const float* lin2_w  = (const float*)d_in[18];
    const float* lin2_b  = (const float*)d_in[19];
    const float* bn7_g   = (const float*)d_in[20];
    const float* bn7_b   = (const float*)d_in[21];
    const float* lin3_w  = (const float*)d_in[22];
    const float* lin3_b  = (const float*)d_in[23];
    float* out = (float*)d_out;

    float *inner, *xxp, *ABp, *Xc, *wbuf, *gp;
    int* idxp;
    __nv_bfloat16 *XA, *Wb, *W5b;
    cudaGetSymbolAddress((void**)&inner, g_inner);
    cudaGetSymbolAddress((void**)&xxp,   g_xx);
    cudaGetSymbolAddress((void**)&idxp,  g_idx);
    cudaGetSymbolAddress((void**)&ABp,   g_AB);
    cudaGetSymbolAddress((void**)&Xc,    g_Xc);
    cudaGetSymbolAddress((void**)&wbuf,  g_wbuf);
    cudaGetSymbolAddress((void**)&gp,    g_gpool);
    cudaGetSymbolAddress((void**)&XA,    g_XA);
    cudaGetSymbolAddress((void**)&Wb,    g_Wb);
    cudaGetSymbolAddress((void**)&W5b,   g_W5b);

    // split fp32 weights, then convert to bf16 layout B per stage
    wsplit_all_kernel<<<(W_TOTAL + 255) / 256, 256>>>(conv1_w, conv2_w, conv3_w, conv4_w, wbuf);
    launch_tobf16(wbuf + W1_OFF, 3,   3,   32,  2, Wb + WB1_OFF, 128 * 96);
    launch_tobf16(wbuf + W2_OFF, 64,  64,  64,  2, Wb + WB2_OFF, 128 * 192);
    launch_tobf16(wbuf + W3_OFF, 64,  64,  64,  2, Wb + WB3_OFF, 256 * 192);
    launch_tobf16(wbuf + W4_OFF, 128, 128, 128, 2, Wb + WB4_OFF, 512 * 384);
    launch_tobf16(conv5_w, 512, 512, 512, 2, W5b, 1024 * 1536);

    // edge conv stages (outputs go straight into concat slices of Xc)
    run_edge_stage(x,        3,   3,   64,  Wb + WB1_OFF, conv1_b,
                   bn1_g, bn1_b, Xc + 0,   inner, xxp, idxp, ABp, XA);
    run_edge_stage(Xc + 0,   512, 64,  64,  Wb + WB2_OFF, nullptr,
                   bn2_g, bn2_b, Xc + 64,  inner, xxp, idxp, ABp, XA);
    run_edge_stage(Xc + 64,  512, 64,  128, Wb + WB3_OFF, nullptr,
                   bn3_g, bn3_b, Xc + 128, inner, xxp, idxp, ABp, XA);
    run_edge_stage(Xc + 128, 512, 128, 256, Wb + WB4_OFF, nullptr,
                   bn4_g, bn4_b, Xc + 256, inner, xxp, idxp, ABp, XA);

    // conv5: convert Xc (layout A, K'=1536), e[b] = XcA @ W5b^T, max over n
    launch_tobf16(Xc, 512, 512, 512, 1, XA, BB * NN * 1536);
    dim3 g5(NN / TBM, NN / TBN, BB);
    gemm_bf16<<<g5, 256>>>(XA, W5b, inner, 1536, 1536, NN, 1536,
                           (long)NN * 1536, 0, (long)NN * NN);
    maxcol_kernel<<<dim3(NN / 256, BB), 256>>>(inner, gp);

    // MLP head
    mlp_head_kernel<<<BB, 512>>>(gp, lin1_w, bn6_g, bn6_b,
                                 lin2_w, lin2_b, bn7_g, bn7_b,
                                 lin3_w, lin3_b, out);
}